// round 1
// baseline (speedup 1.0000x reference)
#include <cuda_runtime.h>

// SSIM-style loss, faithful to the reference's "box" (sum over channels+window, /ws^2).
// x, y: (32, 3, 512, 512) fp32. out: (32,) fp32.
//
// Kernel 1: one CTA per (batch, window-row). 128 threads; thread t owns
// float4-column t (cols 4t..4t+3) over 16 rows x 3 channels. Fully coalesced.
// Width-4 shuffle reduce -> per-window sums -> SSIM -> CTA partial (32 windows).
// Kernel 2: fold 32 partials per batch -> (1 - mean)/2.

#define IMG_H 512
#define IMG_W 512
#define NCH 3
#define WS 16
#define NWIN_X 32              // 512/16
#define NWIN_Y 32
#define NBATCH 32
#define W4 (IMG_W / 4)          // 128 float4 per row

static __device__ float g_partial[NBATCH * NWIN_Y];   // one per CTA

__global__ __launch_bounds__(128, 8)
void ssim_row_kernel(const float* __restrict__ x, const float* __restrict__ y) {
    const int t  = threadIdx.x;            // 0..127 = float4 column
    const int br = blockIdx.x & 31;        // window row
    const int b  = blockIdx.x >> 5;        // batch

    const size_t img = (size_t)NCH * IMG_H * IMG_W;
    const float4* __restrict__ xp = (const float4*)(x + (size_t)b * img);
    const float4* __restrict__ yp = (const float4*)(y + (size_t)b * img);

    float sx = 0.f, sy = 0.f, sxx = 0.f, syy = 0.f, sxy = 0.f;

#pragma unroll
    for (int c = 0; c < NCH; ++c) {
        // base index in float4 units for (channel c, row br*16, col 4t)
        size_t base = (size_t)c * (IMG_H * W4) + (size_t)(br * WS) * W4 + t;
#pragma unroll 8
        for (int h = 0; h < WS; ++h) {
            float4 vx = __ldg(xp + base + (size_t)h * W4);
            float4 vy = __ldg(yp + base + (size_t)h * W4);
            sx += (vx.x + vx.y) + (vx.z + vx.w);
            sy += (vy.x + vy.y) + (vy.z + vy.w);
            sxx = fmaf(vx.x, vx.x, sxx); sxx = fmaf(vx.y, vx.y, sxx);
            sxx = fmaf(vx.z, vx.z, sxx); sxx = fmaf(vx.w, vx.w, sxx);
            syy = fmaf(vy.x, vy.x, syy); syy = fmaf(vy.y, vy.y, syy);
            syy = fmaf(vy.z, vy.z, syy); syy = fmaf(vy.w, vy.w, syy);
            sxy = fmaf(vx.x, vy.x, sxy); sxy = fmaf(vx.y, vy.y, sxy);
            sxy = fmaf(vx.z, vy.z, sxy); sxy = fmaf(vx.w, vy.w, sxy);
        }
    }

    // fold 4 adjacent threads (one 16-col window) via xor butterfly
#pragma unroll
    for (int off = 1; off < 4; off <<= 1) {
        sx  += __shfl_xor_sync(0xffffffffu, sx,  off);
        sy  += __shfl_xor_sync(0xffffffffu, sy,  off);
        sxx += __shfl_xor_sync(0xffffffffu, sxx, off);
        syy += __shfl_xor_sync(0xffffffffu, syy, off);
        sxy += __shfl_xor_sync(0xffffffffu, sxy, off);
    }

    __shared__ float s_ssim[NWIN_X];
    if ((t & 3) == 0) {
        const float inv = 1.0f / (WS * WS);            // /256, as in reference
        const float C1 = 6.5025f;                      // (0.01*255)^2
        const float C2 = 58.5225f;                     // (0.03*255)^2
        float mx = sx * inv, my = sy * inv;
        float vx = sxx * inv - mx * mx;
        float vy = syy * inv - my * my;
        float cv = sxy * inv - mx * my;
        float num = (2.0f * mx * my + C1) * (2.0f * cv + C2);
        float den = (mx * mx + my * my + C1) * (vx + vy + C2);
        s_ssim[t >> 2] = num / den;
    }
    __syncthreads();

    if (t < 32) {
        float v = s_ssim[t];
#pragma unroll
        for (int off = 16; off; off >>= 1)
            v += __shfl_xor_sync(0xffffffffu, v, off);
        if (t == 0) g_partial[blockIdx.x] = v;
    }
}

__global__ void ssim_finalize(float* __restrict__ out) {
    const int b = threadIdx.x;             // 0..31
    float s = 0.f;
#pragma unroll
    for (int i = 0; i < NWIN_Y; ++i)
        s += g_partial[b * NWIN_Y + i];
    out[b] = (1.0f - s * (1.0f / (NWIN_X * NWIN_Y))) * 0.5f;
}

extern "C" void kernel_launch(void* const* d_in, const int* in_sizes, int n_in,
                              void* d_out, int out_size) {
    const float* x = (const float*)d_in[0];
    const float* y = (const float*)d_in[1];
    float* out = (float*)d_out;
    (void)in_sizes; (void)n_in; (void)out_size;

    ssim_row_kernel<<<NBATCH * NWIN_Y, 128>>>(x, y);
    ssim_finalize<<<1, 32>>>(out);
}

// round 2
// speedup vs baseline: 1.0580x; 1.0580x over previous
#include <cuda_runtime.h>

// SSIM-style loss (sum over channels+window, /ws^2), single fused kernel.
// x, y: (32, 3, 512, 512) fp32. out: (32,) fp32.
//
// One CTA per (batch, window-row): 1024 CTAs x 128 threads. Thread t owns
// float4-column t over 16 rows x 3 channels (fully coalesced 2KB/warp-row).
// Loads batched 4 rows deep (8 LDG.128 in flight) for MLP.
// Per-batch ticket counter: last CTA of each batch folds 32 partials -> out[b],
// then resets its counter so CUDA-graph replays are deterministic.

#define IMG_H 512
#define IMG_W 512
#define NCH 3
#define WS 16
#define NWIN_X 32
#define NWIN_Y 32
#define NBATCH 32
#define W4 (IMG_W / 4)

static __device__ float        g_partial[NBATCH * NWIN_Y];
static __device__ unsigned int g_ticket[NBATCH];          // zero-initialized; reset each run

__global__ __launch_bounds__(128)
void ssim_fused_kernel(const float* __restrict__ x, const float* __restrict__ y,
                       float* __restrict__ out) {
    const int t  = threadIdx.x;            // float4 column 0..127
    const int br = blockIdx.x & 31;        // window row
    const int b  = blockIdx.x >> 5;        // batch

    const size_t img = (size_t)NCH * IMG_H * IMG_W;
    const float4* __restrict__ xp = (const float4*)(x + (size_t)b * img);
    const float4* __restrict__ yp = (const float4*)(y + (size_t)b * img);

    float sx = 0.f, sy = 0.f, sxx = 0.f, syy = 0.f, sxy = 0.f;

#pragma unroll
    for (int c = 0; c < NCH; ++c) {
        size_t base = (size_t)c * (IMG_H * W4) + (size_t)(br * WS) * W4 + t;
#pragma unroll
        for (int h0 = 0; h0 < WS; h0 += 4) {
            float4 vx[4], vy[4];
#pragma unroll
            for (int j = 0; j < 4; ++j) {
                vx[j] = __ldg(xp + base + (size_t)(h0 + j) * W4);
                vy[j] = __ldg(yp + base + (size_t)(h0 + j) * W4);
            }
#pragma unroll
            for (int j = 0; j < 4; ++j) {
                sx += (vx[j].x + vx[j].y) + (vx[j].z + vx[j].w);
                sy += (vy[j].x + vy[j].y) + (vy[j].z + vy[j].w);
                sxx = fmaf(vx[j].x, vx[j].x, sxx); sxx = fmaf(vx[j].y, vx[j].y, sxx);
                sxx = fmaf(vx[j].z, vx[j].z, sxx); sxx = fmaf(vx[j].w, vx[j].w, sxx);
                syy = fmaf(vy[j].x, vy[j].x, syy); syy = fmaf(vy[j].y, vy[j].y, syy);
                syy = fmaf(vy[j].z, vy[j].z, syy); syy = fmaf(vy[j].w, vy[j].w, syy);
                sxy = fmaf(vx[j].x, vy[j].x, sxy); sxy = fmaf(vx[j].y, vy[j].y, sxy);
                sxy = fmaf(vx[j].z, vy[j].z, sxy); sxy = fmaf(vx[j].w, vy[j].w, sxy);
            }
        }
    }

    // fold 4 adjacent threads (one 16-col window)
#pragma unroll
    for (int off = 1; off < 4; off <<= 1) {
        sx  += __shfl_xor_sync(0xffffffffu, sx,  off);
        sy  += __shfl_xor_sync(0xffffffffu, sy,  off);
        sxx += __shfl_xor_sync(0xffffffffu, sxx, off);
        syy += __shfl_xor_sync(0xffffffffu, syy, off);
        sxy += __shfl_xor_sync(0xffffffffu, sxy, off);
    }

    __shared__ float s_ssim[NWIN_X];
    __shared__ unsigned int s_ticket;
    if ((t & 3) == 0) {
        const float inv = 1.0f / (WS * WS);
        const float C1 = 6.5025f;
        const float C2 = 58.5225f;
        float mx = sx * inv, my = sy * inv;
        float vx = sxx * inv - mx * mx;
        float vy = syy * inv - my * my;
        float cv = sxy * inv - mx * my;
        float num = (2.0f * mx * my + C1) * (2.0f * cv + C2);
        float den = (mx * mx + my * my + C1) * (vx + vy + C2);
        s_ssim[t >> 2] = num / den;
    }
    __syncthreads();

    if (t < 32) {
        float v = s_ssim[t];
#pragma unroll
        for (int off = 16; off; off >>= 1)
            v += __shfl_xor_sync(0xffffffffu, v, off);
        if (t == 0) {
            g_partial[blockIdx.x] = v;
            __threadfence();
            unsigned int tk = atomicAdd(&g_ticket[b], 1u);
            s_ticket = tk;
        }
    }
    __syncthreads();

    // Last CTA of this batch folds the 32 row-partials.
    if (s_ticket == NWIN_Y - 1) {
        if (t < 32) {
            volatile float* vp = (volatile float*)&g_partial[b * NWIN_Y];
            float v = vp[t];
#pragma unroll
            for (int off = 16; off; off >>= 1)
                v += __shfl_xor_sync(0xffffffffu, v, off);
            if (t == 0) {
                out[b] = (1.0f - v * (1.0f / (NWIN_X * NWIN_Y))) * 0.5f;
                g_ticket[b] = 0u;   // reset for next (graph-replayed) launch
            }
        }
    }
}

extern "C" void kernel_launch(void* const* d_in, const int* in_sizes, int n_in,
                              void* d_out, int out_size) {
    const float* x = (const float*)d_in[0];
    const float* y = (const float*)d_in[1];
    float* out = (float*)d_out;
    (void)in_sizes; (void)n_in; (void)out_size;

    ssim_fused_kernel<<<NBATCH * NWIN_Y, 128>>>(x, y, out);
}